// round 10
// baseline (speedup 1.0000x reference)
#include <cuda_runtime.h>
#include <cuda_bf16.h>
#include <cstdint>

// Problem constants (from reference)
#define B_  8
#define L_  2048
#define P_  576
#define V_  32000
#define D_  2560
#define T_  (L_ - 1 + P_)      // 2623
#define N_ROWS_ (B_ * T_)      // 20984
#define IGNORE_INDEX_ (-100)

// Write-through float4 store: output stream takes no L2 lines.
__device__ __forceinline__ void stwt4(float4* p, float4 v) {
    asm volatile("st.global.wt.v4.f32 [%0], {%1,%2,%3,%4};"
                 :: "l"(p), "f"(v.x), "f"(v.y), "f"(v.z), "f"(v.w)
                 : "memory");
}

// ---------------------------------------------------------------------------
// Kernel 1: payload rows. One block per output row (b, t). 128 threads,
// 640 float4 per row -> exactly 5 unconditional float4 per thread, loads
// front-batched. No scalar tails here (uniform control flow, no scattered
// stores extending CTA lifetimes).
//
// Cache policy:
//   embed_table    -> __ldg  : reused working set, cached in L2
//   image_features -> __ldcs : read-once streaming, evict-first
//   output         -> st.wt  : no L2 footprint (keeps embed rows resident)
// ---------------------------------------------------------------------------
__global__ void __launch_bounds__(128)
splice_rows(const float* __restrict__ embed_table,     // [V, D]
            const float* __restrict__ image_features,  // [B, P, D]
            const int*   __restrict__ input_ids,       // [B, L]
            const int*   __restrict__ img_pos,         // [B]
            float* __restrict__ out)
{
    const int row = blockIdx.x;           // 0 .. B*T-1
    const int b = row / T_;
    const int t = row - b * T_;

    const int pos = img_pos[b];
    const bool is_img = (t >= pos) && (t < pos + P_);

    int tok_idx = (t < pos) ? t : (t - P_ + 1);
    tok_idx = max(0, min(tok_idx, L_ - 1));

    float4* __restrict__ dst =
        reinterpret_cast<float4*>(out + (long long)row * D_);

    const int tid = threadIdx.x;

    if (is_img) {
        const int img_idx = max(0, min(t - pos, P_ - 1));
        const float4* __restrict__ src = reinterpret_cast<const float4*>(
            image_features + ((long long)b * P_ + img_idx) * D_);
        float4 v0 = __ldcs(src + tid);
        float4 v1 = __ldcs(src + tid + 128);
        float4 v2 = __ldcs(src + tid + 256);
        float4 v3 = __ldcs(src + tid + 384);
        float4 v4 = __ldcs(src + tid + 512);
        stwt4(dst + tid,       v0);
        stwt4(dst + tid + 128, v1);
        stwt4(dst + tid + 256, v2);
        stwt4(dst + tid + 384, v3);
        stwt4(dst + tid + 512, v4);
    } else {
        const int tok = input_ids[b * L_ + tok_idx];
        const float4* __restrict__ src = reinterpret_cast<const float4*>(
            embed_table + (long long)tok * D_);
        float4 v0 = __ldg(src + tid);
        float4 v1 = __ldg(src + tid + 128);
        float4 v2 = __ldg(src + tid + 256);
        float4 v3 = __ldg(src + tid + 384);
        float4 v4 = __ldg(src + tid + 512);
        stwt4(dst + tid,       v0);
        stwt4(dst + tid + 128, v1);
        stwt4(dst + tid + 256, v2);
        stwt4(dst + tid + 384, v3);
        stwt4(dst + tid + 512, v4);
    }
}

// ---------------------------------------------------------------------------
// Kernel 2: tails (new_labels / attention_mask / position_ids), fully
// coalesced: thread i handles row i (adjacent threads -> adjacent 4B
// stores -> full 128B lines, one writer per sector).
// ---------------------------------------------------------------------------
__global__ void __launch_bounds__(256)
splice_tails(const int* __restrict__ labels,    // [B, L]
             const int* __restrict__ img_pos,   // [B]
             float* __restrict__ out)
{
    const int row = blockIdx.x * 256 + threadIdx.x;
    if (row >= N_ROWS_) return;

    const int b = row / T_;
    const int t = row - b * T_;

    const int pos = img_pos[b];
    const bool is_img = (t >= pos) && (t < pos + P_);

    int tok_idx = (t < pos) ? t : (t - P_ + 1);
    tok_idx = max(0, min(tok_idx, L_ - 1));

    float* tails = out + (long long)N_ROWS_ * D_;
    // new_labels
    tails[row] = is_img ? (float)IGNORE_INDEX_
                        : (float)labels[b * L_ + tok_idx];
    // attention_mask (all true)
    tails[(long long)N_ROWS_ + row] = 1.0f;
    // position_ids (iota over T)
    tails[2LL * N_ROWS_ + row] = (float)t;
}

extern "C" void kernel_launch(void* const* d_in, const int* in_sizes, int n_in,
                              void* d_out, int out_size)
{
    const float* embed_table    = (const float*)d_in[0];
    const float* image_features = (const float*)d_in[1];
    const int*   input_ids      = (const int*)  d_in[2];
    const int*   labels         = (const int*)  d_in[3];
    const int*   img_pos        = (const int*)  d_in[4];
    float* out = (float*)d_out;

    // Tiny tails kernel first (independent regions; overlaps with the start
    // of the row kernel at wave granularity on replay).
    splice_tails<<<(N_ROWS_ + 255) / 256, 256>>>(labels, img_pos, out);
    splice_rows<<<N_ROWS_, 128>>>(embed_table, image_features,
                                  input_ids, img_pos, out);
}

// round 11
// speedup vs baseline: 1.0281x; 1.0281x over previous
#include <cuda_runtime.h>
#include <cuda_bf16.h>
#include <cstdint>

// Problem constants (from reference)
#define B_  8
#define L_  2048
#define P_  576
#define V_  32000
#define D_  2560
#define T_  (L_ - 1 + P_)      // 2623
#define N_ROWS_ (B_ * T_)      // 20984
#define IGNORE_INDEX_ (-100)

// Tail blocks: 83 blocks x 256 threads covers 20984 rows of coalesced tails.
#define TAIL_BLOCKS_ ((N_ROWS_ + 255) / 256)   // 82 -> need 82? 82*256=20992 >= 20984
#define TOTAL_BLOCKS_ (N_ROWS_ + TAIL_BLOCKS_)

// Write-through float4 store: output stream takes no L2 lines.
__device__ __forceinline__ void stwt4(float4* p, float4 v) {
    asm volatile("st.global.wt.v4.f32 [%0], {%1,%2,%3,%4};"
                 :: "l"(p), "f"(v.x), "f"(v.y), "f"(v.z), "f"(v.w)
                 : "memory");
}

// Single kernel, single launch.
//   Blocks [0, N_ROWS): one output row each. 128 threads, 640 float4/row
//     -> exactly 5 unconditional float4 per thread, loads front-batched.
//     Uniform control flow, no scalar tail work.
//   Blocks [N_ROWS, N_ROWS+TAIL_BLOCKS): coalesced tails. Thread handles one
//     row index; adjacent threads -> adjacent 4B stores -> full 128B lines.
//
// Cache policy:
//   embed_table    -> __ldg  : reused working set, cached in L2
//   image_features -> __ldcs : read-once streaming, evict-first
//   output payload -> st.wt  : no L2 footprint (keeps embed rows resident)
__global__ void __launch_bounds__(128)
splice_kernel(const float* __restrict__ embed_table,     // [V, D]
              const float* __restrict__ image_features,  // [B, P, D]
              const int*   __restrict__ input_ids,       // [B, L]
              const int*   __restrict__ labels,          // [B, L]
              const int*   __restrict__ img_pos,         // [B]
              float* __restrict__ out)
{
    const int blk = blockIdx.x;
    const int tid = threadIdx.x;

    if (blk < N_ROWS_) {
        // ---- payload row ----
        const int row = blk;
        const int b = row / T_;
        const int t = row - b * T_;

        const int pos = img_pos[b];
        const bool is_img = (t >= pos) && (t < pos + P_);

        int tok_idx = (t < pos) ? t : (t - P_ + 1);
        tok_idx = max(0, min(tok_idx, L_ - 1));

        float4* __restrict__ dst =
            reinterpret_cast<float4*>(out + (long long)row * D_);

        if (is_img) {
            const int img_idx = max(0, min(t - pos, P_ - 1));
            const float4* __restrict__ src = reinterpret_cast<const float4*>(
                image_features + ((long long)b * P_ + img_idx) * D_);
            float4 v0 = __ldcs(src + tid);
            float4 v1 = __ldcs(src + tid + 128);
            float4 v2 = __ldcs(src + tid + 256);
            float4 v3 = __ldcs(src + tid + 384);
            float4 v4 = __ldcs(src + tid + 512);
            stwt4(dst + tid,       v0);
            stwt4(dst + tid + 128, v1);
            stwt4(dst + tid + 256, v2);
            stwt4(dst + tid + 384, v3);
            stwt4(dst + tid + 512, v4);
        } else {
            const int tok = input_ids[b * L_ + tok_idx];
            const float4* __restrict__ src = reinterpret_cast<const float4*>(
                embed_table + (long long)tok * D_);
            float4 v0 = __ldg(src + tid);
            float4 v1 = __ldg(src + tid + 128);
            float4 v2 = __ldg(src + tid + 256);
            float4 v3 = __ldg(src + tid + 384);
            float4 v4 = __ldg(src + tid + 512);
            stwt4(dst + tid,       v0);
            stwt4(dst + tid + 128, v1);
            stwt4(dst + tid + 256, v2);
            stwt4(dst + tid + 384, v3);
            stwt4(dst + tid + 512, v4);
        }
    } else {
        // ---- coalesced tails: 128 threads x 2 rows each ----
        const int base = (blk - N_ROWS_) * 256;
        float* tails = out + (long long)N_ROWS_ * D_;

        #pragma unroll
        for (int k = 0; k < 2; k++) {
            const int row = base + tid + k * 128;
            if (row < N_ROWS_) {
                const int b = row / T_;
                const int t = row - b * T_;

                const int pos = img_pos[b];
                const bool is_img = (t >= pos) && (t < pos + P_);

                int tok_idx = (t < pos) ? t : (t - P_ + 1);
                tok_idx = max(0, min(tok_idx, L_ - 1));

                // new_labels
                tails[row] = is_img ? (float)IGNORE_INDEX_
                                    : (float)labels[b * L_ + tok_idx];
                // attention_mask (all true)
                tails[(long long)N_ROWS_ + row] = 1.0f;
                // position_ids (iota over T)
                tails[2LL * N_ROWS_ + row] = (float)t;
            }
        }
    }
}

extern "C" void kernel_launch(void* const* d_in, const int* in_sizes, int n_in,
                              void* d_out, int out_size)
{
    const float* embed_table    = (const float*)d_in[0];
    const float* image_features = (const float*)d_in[1];
    const int*   input_ids      = (const int*)  d_in[2];
    const int*   labels         = (const int*)  d_in[3];
    const int*   img_pos        = (const int*)  d_in[4];
    float* out = (float*)d_out;

    splice_kernel<<<TOTAL_BLOCKS_, 128>>>(embed_table, image_features,
                                          input_ids, labels, img_pos, out);
}

// round 12
// speedup vs baseline: 1.0460x; 1.0174x over previous
#include <cuda_runtime.h>
#include <cuda_bf16.h>
#include <cstdint>

// Problem constants (from reference)
#define B_  8
#define L_  2048
#define P_  576
#define V_  32000
#define D_  2560
#define T_  (L_ - 1 + P_)      // 2623
#define N_ROWS_ (B_ * T_)      // 20984
#define IGNORE_INDEX_ (-100)

// Tail work is folded into the FIRST blocks (wave 0): 82 blocks x 256 tail
// rows covers all 20984 rows; the extra scalar stores hide under the payload
// stream's DRAM latency.
#define TAIL_CHUNK_   256
#define TAIL_BLOCKS_  ((N_ROWS_ + TAIL_CHUNK_ - 1) / TAIL_CHUNK_)   // 82

// Write-through float4 store: output stream takes no L2 lines.
__device__ __forceinline__ void stwt4(float4* p, float4 v) {
    asm volatile("st.global.wt.v4.f32 [%0], {%1,%2,%3,%4};"
                 :: "l"(p), "f"(v.x), "f"(v.y), "f"(v.z), "f"(v.w)
                 : "memory");
}

// One block per output row (b, t). 128 threads, 640 float4 per row ->
// exactly 5 unconditional float4 per thread, loads front-batched.
// Blocks 0..TAIL_BLOCKS-1 additionally write a coalesced 256-row chunk of
// the scalar tails (labels / mask / position_ids) — full 128B sectors,
// single writer per sector, scheduled in the first wave.
//
// Cache policy:
//   embed_table    -> __ldg  : reused working set, cached in L2
//   image_features -> __ldcs : read-once streaming, evict-first
//   output         -> st.wt  : no L2 footprint (keeps embed rows resident)
__global__ void __launch_bounds__(128)
splice_kernel(const float* __restrict__ embed_table,     // [V, D]
              const float* __restrict__ image_features,  // [B, P, D]
              const int*   __restrict__ input_ids,       // [B, L]
              const int*   __restrict__ labels,          // [B, L]
              const int*   __restrict__ img_pos,         // [B]
              float* __restrict__ out)
{
    const int row = blockIdx.x;           // 0 .. B*T-1
    const int b = row / T_;
    const int t = row - b * T_;

    const int pos = img_pos[b];
    const bool is_img = (t >= pos) && (t < pos + P_);

    int tok_idx = (t < pos) ? t : (t - P_ + 1);
    tok_idx = max(0, min(tok_idx, L_ - 1));

    float4* __restrict__ dst =
        reinterpret_cast<float4*>(out + (long long)row * D_);

    const int tid = threadIdx.x;

    if (is_img) {
        const int img_idx = max(0, min(t - pos, P_ - 1));
        const float4* __restrict__ src = reinterpret_cast<const float4*>(
            image_features + ((long long)b * P_ + img_idx) * D_);
        float4 v0 = __ldcs(src + tid);
        float4 v1 = __ldcs(src + tid + 128);
        float4 v2 = __ldcs(src + tid + 256);
        float4 v3 = __ldcs(src + tid + 384);
        float4 v4 = __ldcs(src + tid + 512);
        stwt4(dst + tid,       v0);
        stwt4(dst + tid + 128, v1);
        stwt4(dst + tid + 256, v2);
        stwt4(dst + tid + 384, v3);
        stwt4(dst + tid + 512, v4);
    } else {
        const int tok = input_ids[b * L_ + tok_idx];
        const float4* __restrict__ src = reinterpret_cast<const float4*>(
            embed_table + (long long)tok * D_);
        float4 v0 = __ldg(src + tid);
        float4 v1 = __ldg(src + tid + 128);
        float4 v2 = __ldg(src + tid + 256);
        float4 v3 = __ldg(src + tid + 384);
        float4 v4 = __ldg(src + tid + 512);
        stwt4(dst + tid,       v0);
        stwt4(dst + tid + 128, v1);
        stwt4(dst + tid + 256, v2);
        stwt4(dst + tid + 384, v3);
        stwt4(dst + tid + 512, v4);
    }

    // Coalesced tails, handled by the first TAIL_BLOCKS_ blocks (wave 0).
    if (row < TAIL_BLOCKS_) {
        float* tails = out + (long long)N_ROWS_ * D_;
        const int base = row * TAIL_CHUNK_;

        #pragma unroll
        for (int k = 0; k < 2; k++) {
            const int r = base + tid + k * 128;
            if (r < N_ROWS_) {
                const int bb = r / T_;
                const int tt = r - bb * T_;

                const int pp = img_pos[bb];
                const bool im = (tt >= pp) && (tt < pp + P_);

                int ti = (tt < pp) ? tt : (tt - P_ + 1);
                ti = max(0, min(ti, L_ - 1));

                // new_labels
                tails[r] = im ? (float)IGNORE_INDEX_
                              : (float)labels[bb * L_ + ti];
                // attention_mask (all true)
                tails[(long long)N_ROWS_ + r] = 1.0f;
                // position_ids (iota over T)
                tails[2LL * N_ROWS_ + r] = (float)tt;
            }
        }
    }
}

extern "C" void kernel_launch(void* const* d_in, const int* in_sizes, int n_in,
                              void* d_out, int out_size)
{
    const float* embed_table    = (const float*)d_in[0];
    const float* image_features = (const float*)d_in[1];
    const int*   input_ids      = (const int*)  d_in[2];
    const int*   labels         = (const int*)  d_in[3];
    const int*   img_pos        = (const int*)  d_in[4];
    float* out = (float*)d_out;

    splice_kernel<<<N_ROWS_, 128>>>(embed_table, image_features,
                                    input_ids, labels, img_pos, out);
}

// round 13
// speedup vs baseline: 1.0465x; 1.0005x over previous
#include <cuda_runtime.h>
#include <cuda_bf16.h>
#include <cstdint>

// Problem constants (from reference)
#define B_  8
#define L_  2048
#define P_  576
#define V_  32000
#define D_  2560
#define T_  (L_ - 1 + P_)      // 2623
#define IGNORE_INDEX_ (-100)

// Write-through float4 store: output stream takes no L2 lines.
__device__ __forceinline__ void stwt4(float4* p, float4 v) {
    asm volatile("st.global.wt.v4.f32 [%0], {%1,%2,%3,%4};"
                 :: "l"(p), "f"(v.x), "f"(v.y), "f"(v.z), "f"(v.w)
                 : "memory");
}

// Champion kernel (session best: 66.0us dur, 59.4us kernel, 6.0TB/s).
//
// One block per output row (b, t). 128 threads, 640 float4 per row ->
// exactly 5 unconditional float4 per thread, loads front-batched (MLP=5).
//
// Cache policy (the load-bearing part):
//   embed_table    -> __ldg  : reused working set (~128MB), cached in L2;
//                              repeated rows dedup'd by L2
//   image_features -> __ldcs : read-once streaming, evict-first
//   output         -> st.wt  : write-through, no L2 allocation — keeps the
//                              215MB output stream from evicting embed rows
//
// Scalar tails via tid0 per block: measured free (hidden under DRAM latency;
// R10/R11/R12 ablations all within noise or worse).
__global__ void __launch_bounds__(128)
splice_kernel(const float* __restrict__ embed_table,     // [V, D]
              const float* __restrict__ image_features,  // [B, P, D]
              const int*   __restrict__ input_ids,       // [B, L]
              const int*   __restrict__ labels,          // [B, L]
              const int*   __restrict__ img_pos,         // [B]
              float* __restrict__ out)
{
    const int row = blockIdx.x;           // 0 .. B*T-1
    const int b = row / T_;
    const int t = row - b * T_;

    const int pos = img_pos[b];
    const bool is_img = (t >= pos) && (t < pos + P_);

    int tok_idx = (t < pos) ? t : (t - P_ + 1);
    tok_idx = max(0, min(tok_idx, L_ - 1));

    float4* __restrict__ dst =
        reinterpret_cast<float4*>(out + (long long)row * D_);

    const int tid = threadIdx.x;

    if (is_img) {
        const int img_idx = max(0, min(t - pos, P_ - 1));
        const float4* __restrict__ src = reinterpret_cast<const float4*>(
            image_features + ((long long)b * P_ + img_idx) * D_);
        float4 v0 = __ldcs(src + tid);
        float4 v1 = __ldcs(src + tid + 128);
        float4 v2 = __ldcs(src + tid + 256);
        float4 v3 = __ldcs(src + tid + 384);
        float4 v4 = __ldcs(src + tid + 512);
        stwt4(dst + tid,       v0);
        stwt4(dst + tid + 128, v1);
        stwt4(dst + tid + 256, v2);
        stwt4(dst + tid + 384, v3);
        stwt4(dst + tid + 512, v4);
    } else {
        const int tok = input_ids[b * L_ + tok_idx];
        const float4* __restrict__ src = reinterpret_cast<const float4*>(
            embed_table + (long long)tok * D_);
        float4 v0 = __ldg(src + tid);
        float4 v1 = __ldg(src + tid + 128);
        float4 v2 = __ldg(src + tid + 256);
        float4 v3 = __ldg(src + tid + 384);
        float4 v4 = __ldg(src + tid + 512);
        stwt4(dst + tid,       v0);
        stwt4(dst + tid + 128, v1);
        stwt4(dst + tid + 256, v2);
        stwt4(dst + tid + 384, v3);
        stwt4(dst + tid + 512, v4);
    }

    if (tid == 0) {
        float* tails = out + (long long)B_ * T_ * D_;
        // new_labels
        tails[row] = is_img ? (float)IGNORE_INDEX_
                            : (float)labels[b * L_ + tok_idx];
        // attention_mask (all true)
        tails[(long long)B_ * T_ + row] = 1.0f;
        // position_ids (iota over T)
        tails[2LL * B_ * T_ + row] = (float)t;
    }
}

extern "C" void kernel_launch(void* const* d_in, const int* in_sizes, int n_in,
                              void* d_out, int out_size)
{
    const float* embed_table    = (const float*)d_in[0];
    const float* image_features = (const float*)d_in[1];
    const int*   input_ids      = (const int*)  d_in[2];
    const int*   labels         = (const int*)  d_in[3];
    const int*   img_pos        = (const int*)  d_in[4];
    float* out = (float*)d_out;

    const int n_rows = B_ * T_;   // 20984
    splice_kernel<<<n_rows, 128>>>(embed_table, image_features,
                                   input_ids, labels, img_pos, out);
}